// round 11
// baseline (speedup 1.0000x reference)
#include <cuda_runtime.h>
#include <cstdint>

#define NBOX   8192
#define CLS    81
#define NPAD   300
#define NWORDS (NBOX / 32)      // 256 words per mask row
#define NCH2   (NBOX / 128)     // 64 scan chunks of 128 boxes

// ------------------------- device scratch (static, no allocs) --------------
__device__ float4             g_selv[NBOX];     // decoded boxes (orig order)
__device__ unsigned long long g_key[NBOX];      // composite sort keys
__device__ float4             g_sbox[NBOX];     // boxes in sorted order
__device__ float              g_sarea[NBOX];    // areas in sorted order
__device__ int                g_orig[NBOX];     // sorted pos -> original idx
__device__ unsigned           g_masks[(size_t)NBOX * NWORDS]; // sorted-space IoU>0.5

// ---------------------------------------------------------------------------
// Kernel 1: per-row argmax / max + bbox decode + sort-key build. 1 warp/row.
// ---------------------------------------------------------------------------
__global__ void decode_kernel(const float* __restrict__ meta,
                              const float* __restrict__ deltas,
                              const float* __restrict__ proposals,
                              const float* __restrict__ scores) {
    int row  = (int)((blockIdx.x * blockDim.x + threadIdx.x) >> 5);
    int lane = threadIdx.x & 31;
    if (row >= NBOX) return;

    const float* srow = scores + (size_t)row * CLS;
    float best = -1.0f;
    int   bidx = 0x7FFFFFFF;
    float ms   = -1.0f;
    for (int j = lane; j < CLS; j += 32) {
        float v = srow[j];
        if (v > best) { best = v; bidx = j; }
        if (j >= 1) ms = fmaxf(ms, v);
    }
    #pragma unroll
    for (int off = 16; off; off >>= 1) {
        float ov = __shfl_down_sync(0xffffffffu, best, off);
        int   oi = __shfl_down_sync(0xffffffffu, bidx, off);
        float om = __shfl_down_sync(0xffffffffu, ms,   off);
        if (ov > best || (ov == best && oi < bidx)) { best = ov; bidx = oi; }
        ms = fmaxf(ms, om);
    }

    if (lane == 0) {
        float scale = meta[2];
        const float* p = proposals + (size_t)row * 4;
        float x1 = p[0] / scale, y1 = p[1] / scale;
        float x2 = p[2] / scale, y2 = p[3] / scale;
        float w  = x2 - x1 + 1.0f, h = y2 - y1 + 1.0f;
        float cx = x1 + 0.5f * w,  cy = y1 + 0.5f * h;

        const float* d = deltas + (size_t)row * (4 * CLS) + 4 * bidx;
        float pcx = d[0] * w + cx;
        float pcy = d[1] * h + cy;
        float pw  = expf(d[2]) * w;
        float ph  = expf(d[3]) * h;

        float W1 = meta[1] - 1.0f;
        float H1 = meta[0] - 1.0f;
        float ox1 = fminf(fmaxf(pcx - 0.5f * pw, 0.0f), W1);
        float oy1 = fminf(fmaxf(pcy - 0.5f * ph, 0.0f), H1);
        float ox2 = fminf(fmaxf(pcx + 0.5f * pw, 0.0f), W1);
        float oy2 = fminf(fmaxf(pcy + 0.5f * ph, 0.0f), H1);

        g_selv[row] = make_float4(ox1, oy1, ox2, oy2);
        unsigned int sb = __float_as_uint(ms);   // scores >= 0 -> monotonic bits
        g_key[row] = ((unsigned long long)sb << 13) |
                     (unsigned long long)(8191 - row);   // all keys distinct
    }
}

// ---------------------------------------------------------------------------
// Kernel 2: rank-by-counting + scatter into sorted order. 256 blocks.
// ---------------------------------------------------------------------------
__global__ void __launch_bounds__(256)
rank_kernel() {
    extern __shared__ unsigned long long keys[];   // 64 KB
    const int tid = threadIdx.x;
    for (int i = tid; i < NBOX; i += 256) keys[i] = g_key[i];
    __syncthreads();

    const int warp = tid >> 5, lane = tid & 31;
    const int row0 = blockIdx.x * 32 + warp * 4;

    unsigned long long rk0 = keys[row0 + 0];
    unsigned long long rk1 = keys[row0 + 1];
    unsigned long long rk2 = keys[row0 + 2];
    unsigned long long rk3 = keys[row0 + 3];
    int c0 = 0, c1 = 0, c2 = 0, c3 = 0;

    #pragma unroll 4
    for (int c = lane; c < NBOX; c += 32) {
        unsigned long long kc = keys[c];
        c0 += (kc > rk0);
        c1 += (kc > rk1);
        c2 += (kc > rk2);
        c3 += (kc > rk3);
    }
    #pragma unroll
    for (int off = 16; off; off >>= 1) {
        c0 += __shfl_down_sync(0xffffffffu, c0, off);
        c1 += __shfl_down_sync(0xffffffffu, c1, off);
        c2 += __shfl_down_sync(0xffffffffu, c2, off);
        c3 += __shfl_down_sync(0xffffffffu, c3, off);
    }
    if (lane == 0) {
        int rr[4] = {c0, c1, c2, c3};
        #pragma unroll
        for (int q = 0; q < 4; q++) {
            int i = row0 + q, r = rr[q];
            float4 b = g_selv[i];
            g_sbox[r]  = b;
            g_sarea[r] = fmaxf(b.z - b.x, 0.0f) * fmaxf(b.w - b.y, 0.0f);
            g_orig[r]  = i;
        }
    }
}

// ---------------------------------------------------------------------------
// Kernel 3: sorted-space IoU>0.5 bitmask, upper-triangle tiles only.
// ---------------------------------------------------------------------------
__constant__ int c_prefix[9] = {0, 256, 480, 672, 832, 960, 1056, 1120, 1152};

__global__ void __launch_bounds__(256)
mask_kernel() {
    __shared__ float4 rbs[32];
    __shared__ float  ras[32];
    __shared__ float4 cbT[32 * 33];
    __shared__ float  caT[32 * 33];

    const int t = blockIdx.x;
    int g = 0;
    #pragma unroll
    for (int h = 1; h < 8; h++) g += (t >= c_prefix[h]);
    const int tp   = t - c_prefix[g];
    const int span = 8 - g;
    const int r    = tp / span;
    const int rb   = g * 32 + r;
    const int cb   = g + (tp - r * span);

    const int rowbase = rb * 32;
    const int colbase = cb * 1024;
    const int tid = threadIdx.x;

    if (tid < 32) {
        rbs[tid] = g_sbox[rowbase + tid];
        ras[tid] = g_sarea[rowbase + tid];
    }
    for (int jj = tid; jj < 1024; jj += 256) {
        int w = jj >> 5, bb = jj & 31;
        cbT[bb * 33 + w] = g_sbox[colbase + jj];
        caT[bb * 33 + w] = g_sarea[colbase + jj];
    }
    __syncthreads();

    const int r0 = tid >> 5;
    const int w  = tid & 31;
    float4 bi[4];
    float  si[4];
    #pragma unroll
    for (int k = 0; k < 4; k++) {
        bi[k] = rbs[r0 + 8 * k];
        si[k] = ras[r0 + 8 * k] + 1e-8f;
    }
    unsigned bits0 = 0, bits1 = 0, bits2 = 0, bits3 = 0;

    #pragma unroll
    for (int b = 0; b < 32; b++) {
        float4 bj = cbT[b * 33 + w];
        float  aj = caT[b * 33 + w];
        #pragma unroll
        for (int k = 0; k < 4; k++) {
            float xx1 = fmaxf(bi[k].x, bj.x), yy1 = fmaxf(bi[k].y, bj.y);
            float xx2 = fminf(bi[k].z, bj.z), yy2 = fminf(bi[k].w, bj.w);
            float iw  = fmaxf(xx2 - xx1, 0.0f);
            float ih  = fmaxf(yy2 - yy1, 0.0f);
            float inter = iw * ih;
            unsigned p = (3.0f * inter > si[k] + aj) ? (1u << b) : 0u;
            if (k == 0) bits0 |= p;
            else if (k == 1) bits1 |= p;
            else if (k == 2) bits2 |= p;
            else bits3 |= p;
        }
    }
    size_t base = (size_t)rowbase * NWORDS + (size_t)cb * 32 + w;
    g_masks[base + (size_t)(r0 +  0) * NWORDS] = bits0;
    g_masks[base + (size_t)(r0 +  8) * NWORDS] = bits1;
    g_masks[base + (size_t)(r0 + 16) * NWORDS] = bits2;
    g_masks[base + (size_t)(r0 + 24) * NWORDS] = bits3;
}

// ---------------------------------------------------------------------------
// Kernel 4: greedy scan, 128-box chunks. All loads one-chunk-delayed:
//  operands: LDG at iter c-1 (regs) -> STS at iter c -> read at iter c+1
//  keep rows: LDG at iter c -> shift at c+1 -> applied to sup_s at c+2
//  No warp blocks on a fresh load before the barrier.
// ---------------------------------------------------------------------------
__global__ void __launch_bounds__(256)
scan_kernel(const float* __restrict__ scores, float* __restrict__ out) {
    __shared__ unsigned           sup_s[NWORDS];
    __shared__ unsigned long long kbuf[2][2];
    __shared__ int                kcnt[2];
    __shared__ int                s_keep[NPAD];
    __shared__ unsigned long long confb[2][128][2];
    __shared__ unsigned long long n1b[2][128][2];
    __shared__ unsigned long long n2b[2][128][2];

    const int tid = threadIdx.x;
    sup_s[tid] = 0u;
    if (tid == 0) {
        kbuf[0][0] = kbuf[0][1] = kbuf[1][0] = kbuf[1][1] = 0ull;
        kcnt[0] = kcnt[1] = 0;
    }

    // per-thread operand tasks (tid>=32): tasks tid-32 and tid-32+224 of 384
    const int t0_ = tid - 32;
    const int t1_ = (t0_ >= 0 && t0_ + 224 < 384) ? t0_ + 224 : -1;
    uint4 opr0 = make_uint4(0, 0, 0, 0), opr1 = make_uint4(0, 0, 0, 0);

    // ---- prologue: fill chunk 0 buffers; preload chunk 1 into registers ---
    if (tid >= 32) {
        #pragma unroll
        for (int q = 0; q < 2; q++) {
            int t = q ? t1_ : t0_;
            if (t < 0) continue;
            int row = t & 127, f = t >> 7;
            // chunk 0
            uint4 v = __ldg((const uint4*)(g_masks + (size_t)row * NWORDS + 4 * f));
            unsigned long long lo = (unsigned long long)v.x | ((unsigned long long)v.y << 32);
            unsigned long long hi = (unsigned long long)v.z | ((unsigned long long)v.w << 32);
            if (f == 0)      { confb[0][row][0] = lo; confb[0][row][1] = hi; }
            else if (f == 1) { n1b[0][row][0] = lo;   n1b[0][row][1] = hi; }
            else             { n2b[0][row][0] = lo;   n2b[0][row][1] = hi; }
            // chunk 1 -> registers
            int w = 4 + 4 * f; if (w > NWORDS - 4) w = NWORDS - 4;
            uint4 v1 = __ldg((const uint4*)(g_masks + (size_t)(128 + row) * NWORDS + w));
            if (q == 0) opr0 = v1; else opr1 = v1;
        }
    }
    __syncthreads();

    unsigned long long supfix0 = 0, supfix1 = 0, carry0 = 0, carry1 = 0; // t0
    unsigned b1a = 0u, b1b = 0u, b2a = 0u, b2b = 0u;   // keep-row pipeline
    const int w0 = tid - 32;
    const int w1 = (w0 >= 0 && w0 < 32) ? w0 + 224 : -1;
    int nk_local = 0;                                   // t0 only

    for (int c = 0; c < NCH2; c++) {
        // stage A: apply keep-row suppression loaded 2 iters ago (keeps c-3)
        if (tid >= 32) {
            if (b2a) sup_s[w0] |= b2a;
            if (w1 >= 0 && b2b) sup_s[w1] |= b2b;
        }
        __syncthreads();
        if (c > 0 && kcnt[(c - 1) & 1] >= NPAD) break;   // uniform

        if (tid == 0) {
            const int b    = c & 1;
            const int base = c * 128;
            unsigned long long sup0 = *(const unsigned long long*)&sup_s[4 * c];
            unsigned long long sup1 = *(const unsigned long long*)&sup_s[4 * c + 2];
            unsigned long long am0 = ~(sup0 | supfix0);
            unsigned long long am1 = ~(sup1 | supfix1);
            unsigned long long k0 = 0, k1 = 0;
            unsigned long long n1a0 = 0, n1a1 = 0, n2a0 = 0, n2a1 = 0;
            int k2 = nk_local;
            while (am0 | am1) {
                int idx;
                if (am0) idx = __ffsll((long long)am0) - 1;
                else     idx = 64 + __ffsll((long long)am1) - 1;
                if (idx < 64) k0 |= 1ull << idx;
                else          k1 |= 1ull << (idx - 64);
                n1a0 |= n1b[b][idx][0];  n1a1 |= n1b[b][idx][1];
                n2a0 |= n2b[b][idx][0];  n2a1 |= n2b[b][idx][1];
                am0 &= ~confb[b][idx][0];
                am1 &= ~confb[b][idx][1];
                if (idx < 64) am0 &= ~(1ull << idx);
                else          am1 &= ~(1ull << (idx - 64));
                if (k2 < NPAD) s_keep[k2++] = base + idx;
            }
            kbuf[b][0] = k0; kbuf[b][1] = k1;
            kcnt[b] = k2;  nk_local = k2;
            supfix0 = carry0 | n1a0;  supfix1 = carry1 | n1a1;
            carry0  = n2a0;           carry1  = n2a1;
        } else if (tid >= 32) {
            // (1) STS operands for chunk c+1 (registers loaded at iter c-1)
            const int cn = c + 1;
            if (cn < NCH2) {
                const int d = cn & 1;
                #pragma unroll
                for (int q = 0; q < 2; q++) {
                    int t = q ? t1_ : t0_;
                    if (t < 0) continue;
                    uint4 v = q ? opr1 : opr0;
                    int row = t & 127, f = t >> 7;
                    unsigned long long lo = (unsigned long long)v.x | ((unsigned long long)v.y << 32);
                    unsigned long long hi = (unsigned long long)v.z | ((unsigned long long)v.w << 32);
                    if (f == 0)      { confb[d][row][0] = lo; confb[d][row][1] = hi; }
                    else if (f == 1) { n1b[d][row][0] = lo;   n1b[d][row][1] = hi; }
                    else             { n2b[d][row][0] = lo;   n2b[d][row][1] = hi; }
                }
            }
            // (2) LDG operands for chunk c+2 into registers
            const int cf = c + 2;
            if (cf < NCH2) {
                #pragma unroll
                for (int q = 0; q < 2; q++) {
                    int t = q ? t1_ : t0_;
                    if (t < 0) continue;
                    int row = t & 127, f = t >> 7;
                    int w = 4 * cf + 4 * f;
                    if (w > NWORDS - 4) w = NWORDS - 4;
                    uint4 v = __ldg((const uint4*)
                        (g_masks + (size_t)(128 * cf + row) * NWORDS + w));
                    if (q == 0) opr0 = v; else opr1 = v;
                }
            }
            // (3) keep-row pipeline: shift old loads toward apply, issue new
            b2a = b1a; b2b = b1b;
            unsigned a0 = 0u, a1 = 0u;
            if (c > 0) {
                unsigned long long km0 = kbuf[(c - 1) & 1][0];
                unsigned long long km1 = kbuf[(c - 1) & 1][1];
                const size_t pb = (size_t)(c - 1) * 128;
                while (km0) {
                    int l = __ffsll((long long)km0) - 1; km0 &= km0 - 1;
                    const unsigned* row = &g_masks[(pb + l) * NWORDS];
                    a0 |= __ldg(row + w0);
                    if (w1 >= 0) a1 |= __ldg(row + w1);
                }
                while (km1) {
                    int l = __ffsll((long long)km1) - 1; km1 &= km1 - 1;
                    const unsigned* row = &g_masks[(pb + 64 + l) * NWORDS];
                    a0 |= __ldg(row + w0);
                    if (w1 >= 0) a1 |= __ldg(row + w1);
                }
            }
            b1a = a0;  b1b = a1;
        }
    }
    __syncthreads();
    const int nk = (kcnt[0] > kcnt[1]) ? kcnt[0] : kcnt[1];

    // ---- outputs: boxes (300*4) then scores (300*81); zero invalid rows ----
    for (int idx = tid; idx < NPAD * 4; idx += 256) {
        int r = idx >> 2, cc = idx & 3;
        float v = 0.0f;
        if (r < nk) {
            float4 b = g_sbox[s_keep[r]];
            v = (cc == 0) ? b.x : (cc == 1) ? b.y : (cc == 2) ? b.z : b.w;
        }
        out[idx] = v;
    }
    for (int idx = tid; idx < NPAD * CLS; idx += 256) {
        int r = idx / CLS, cc = idx - r * CLS;
        float v = 0.0f;
        if (r < nk)
            v = scores[(size_t)g_orig[s_keep[r]] * CLS + cc];
        out[NPAD * 4 + idx] = v;
    }
}

// ---------------------------------------------------------------------------
extern "C" void kernel_launch(void* const* d_in, const int* in_sizes, int n_in,
                              void* d_out, int out_size) {
    const float* meta      = (const float*)d_in[0];
    const float* deltas    = (const float*)d_in[1];
    const float* proposals = (const float*)d_in[2];
    const float* scores    = (const float*)d_in[3];
    float* out = (float*)d_out;

    decode_kernel<<<NBOX / 8, 256>>>(meta, deltas, proposals, scores);

    cudaFuncSetAttribute(rank_kernel,
                         cudaFuncAttributeMaxDynamicSharedMemorySize, 65536);
    rank_kernel<<<256, 256, 65536>>>();

    mask_kernel<<<1152, 256>>>();

    scan_kernel<<<1, 256>>>(scores, out);
}